// round 2
// baseline (speedup 1.0000x reference)
#include <cuda_runtime.h>
#include <cuda_bf16.h>
#include <cstdint>
#include <cstddef>

// ---------------- problem constants ----------------
#define B_SZ   256
#define T_SZ   1024
#define I_SZ   128
#define H_SZ   256
#define KDIM   (H_SZ + I_SZ)     // 384
#define CLC    8                 // CTAs per cluster (hidden split)
#define NB     16                // batch rows per cluster
#define NGRP   (B_SZ / NB)       // 16 clusters
#define GRID_CTAS (NGRP * CLC)   // 128 CTAs
#define THREADS 128

// SMEM layout (floats)
#define B_STRIDE 388                       // padded row stride for Bs [16][388]
#define A_ELEMS  (KDIM * 128)              // A_T[k][r], k-major, 49152 floats
#define B_ELEMS  (NB * B_STRIDE)           // 6208 floats
#define SMEM_FLOATS (A_ELEMS + B_ELEMS)
#define SMEM_BYTES  (SMEM_FLOATS * 4)      // 221440 bytes

// ping-pong short-state exchange buffer (L2)
__device__ float g_shortbuf[2][B_SZ * H_SZ];

// ---------------- helpers ----------------
__device__ __forceinline__ float sigm(float x) {
    return 1.0f / (1.0f + __expf(-x));
}
__device__ __forceinline__ float tanh_(float x) {
    float e = __expf(-2.0f * fabsf(x));
    float r = (1.0f - e) / (1.0f + e);
    return copysignf(r, x);
}
__device__ __forceinline__ void cluster_sync() {
    asm volatile("barrier.cluster.arrive.aligned;" ::: "memory");
    asm volatile("barrier.cluster.wait.aligned;"   ::: "memory");
}

// ---------------- kernel ----------------
__global__ void __launch_bounds__(THREADS, 1) __cluster_dims__(CLC, 1, 1)
lstm_persistent_kernel(const float* __restrict__ x,
                       const float* __restrict__ Wf_h,  const float* __restrict__ Wf_x,  const float* __restrict__ bf,
                       const float* __restrict__ Wip_h, const float* __restrict__ Wip_x, const float* __restrict__ bip,
                       const float* __restrict__ Wit_h, const float* __restrict__ Wit_x, const float* __restrict__ bit_,
                       const float* __restrict__ Wo_h,  const float* __restrict__ Wo_x,  const float* __restrict__ bo,
                       float* __restrict__ out)
{
    extern __shared__ float smem[];
    float* As = smem;             // A_T[k][r]: k-major, stride 128, r = 4*h_local + gate
    float* Bs = smem + A_ELEMS;   // Bs[i][k]:  row-major, stride 388

    const int tid = threadIdx.x;
    const int c   = blockIdx.x & (CLC - 1);   // cluster rank = hidden-slice owner
    const int grp = blockIdx.x >> 3;          // batch group
    const int b0  = grp * NB;

    // ---- one-time weight staging: row r = tid -> (h_stage = tid>>2, gate g = tid&3)
    {
        const int g  = tid & 3;
        const int hs = 32 * c + (tid >> 2);
        const float* Wh = (g == 0) ? Wf_h : (g == 1) ? Wip_h : (g == 2) ? Wit_h : Wo_h;
        const float* Wx = (g == 0) ? Wf_x : (g == 1) ? Wip_x : (g == 2) ? Wit_x : Wo_x;
        #pragma unroll 4
        for (int k = 0; k < H_SZ; k++)
            As[k * 128 + tid] = Wh[k * H_SZ + hs];
        #pragma unroll 4
        for (int k = 0; k < I_SZ; k++)
            As[(H_SZ + k) * 128 + tid] = Wx[k * H_SZ + hs];
    }

    // ---- compute mapping: h_local = tid & 31, batch group bg = tid >> 5
    const int h_local = tid & 31;
    const int bg      = tid >> 5;
    const int hg      = 32 * c + h_local;     // global hidden index

    const float bfv  = bf[hg];
    const float bipv = bip[hg];
    const float bitv = bit_[hg];
    const float bov  = bo[hg];

    // ---- zero step-0 read buffer (this thread's 4 epilogue cells)
    #pragma unroll
    for (int j = 0; j < 4; j++)
        __stcg(&g_shortbuf[0][(b0 + bg * 4 + j) * H_SZ + hg], 0.0f);

    __syncthreads();
    cluster_sync();

    float longv[4] = {0.0f, 0.0f, 0.0f, 0.0f};

    const float* As_thr = As + 4 * h_local;       // + k*128 per k
    const float* Bs_thr = Bs + (bg * 4) * B_STRIDE;

    #pragma unroll 1
    for (int t = 0; t < T_SZ; t++) {
        const int cur = t & 1;
        const int nxt = cur ^ 1;
        const float* sread = g_shortbuf[cur];

        // ===== stage B operand: Bs[i][0:256) = short, Bs[i][256:384) = x[b][t] =====
        #pragma unroll
        for (int it = 0; it < 12; it++) {
            int u  = tid + THREADS * it;      // 0..1535
            int i  = u / 96;                  // batch row 0..15
            int kq = u - i * 96;              // float4 index 0..95
            float4 v;
            if (kq < 64) {
                v = __ldcg((const float4*)(sread + (size_t)(b0 + i) * H_SZ + 4 * kq));
            } else {
                v = *(const float4*)(x + ((size_t)(b0 + i) * T_SZ + t) * I_SZ + 4 * (kq - 64));
            }
            *(float4*)(Bs + i * B_STRIDE + 4 * kq) = v;
        }
        __syncthreads();

        // ===== GEMM: acc[g][j] = sum_k A_T[k][4h+g] * Bs[4bg+j][k] =====
        float acc[4][4];
        #pragma unroll
        for (int g = 0; g < 4; g++)
            #pragma unroll
            for (int j = 0; j < 4; j++)
                acc[g][j] = 0.0f;

        #pragma unroll 4
        for (int k = 0; k < KDIM; k += 4) {
            float4 a0 = *(const float4*)(As_thr + (k + 0) * 128);
            float4 a1 = *(const float4*)(As_thr + (k + 1) * 128);
            float4 a2 = *(const float4*)(As_thr + (k + 2) * 128);
            float4 a3 = *(const float4*)(As_thr + (k + 3) * 128);
            float4 bv[4];
            #pragma unroll
            for (int j = 0; j < 4; j++)
                bv[j] = *(const float4*)(Bs_thr + j * B_STRIDE + k);  // broadcast
            #pragma unroll
            for (int j = 0; j < 4; j++) {
                acc[0][j] += a0.x * bv[j].x; acc[1][j] += a0.y * bv[j].x;
                acc[2][j] += a0.z * bv[j].x; acc[3][j] += a0.w * bv[j].x;
                acc[0][j] += a1.x * bv[j].y; acc[1][j] += a1.y * bv[j].y;
                acc[2][j] += a1.z * bv[j].y; acc[3][j] += a1.w * bv[j].y;
                acc[0][j] += a2.x * bv[j].z; acc[1][j] += a2.y * bv[j].z;
                acc[2][j] += a2.z * bv[j].z; acc[3][j] += a2.w * bv[j].z;
                acc[0][j] += a3.x * bv[j].w; acc[1][j] += a3.y * bv[j].w;
                acc[2][j] += a3.z * bv[j].w; acc[3][j] += a3.w * bv[j].w;
            }
        }

        // ===== epilogue: gates, state update, publish new_short =====
        #pragma unroll
        for (int j = 0; j < 4; j++) {
            const int bb = b0 + bg * 4 + j;
            float f  = sigm(acc[0][j] + bfv);
            float ip = sigm(acc[1][j] + bipv);
            float pt = tanh_(acc[2][j] + bitv);
            longv[j] = f * longv[j] + ip * pt;
            float o  = sigm(acc[3][j] + bov);
            float ns = tanh_(longv[j]) * o;
            __stcg(&g_shortbuf[nxt][bb * H_SZ + hg], ns);
            if (t == T_SZ - 1) {
                out[bb * H_SZ + hg]                  = ns;        // short
                out[B_SZ * H_SZ + bb * H_SZ + hg]    = longv[j];  // long
            }
        }

        // release new_short to cluster peers, acquire for next step's reads;
        // also serves as the block barrier protecting Bs reuse.
        cluster_sync();
    }
}

// ---------------- launch ----------------
extern "C" void kernel_launch(void* const* d_in, const int* in_sizes, int n_in,
                              void* d_out, int out_size)
{
    (void)in_sizes; (void)n_in; (void)out_size;
    const float* x     = (const float*)d_in[0];
    const float* Wf_h  = (const float*)d_in[1];
    const float* Wf_x  = (const float*)d_in[2];
    const float* bf    = (const float*)d_in[3];
    const float* Wip_h = (const float*)d_in[4];
    const float* Wip_x = (const float*)d_in[5];
    const float* bip   = (const float*)d_in[6];
    const float* Wit_h = (const float*)d_in[7];
    const float* Wit_x = (const float*)d_in[8];
    const float* bit_  = (const float*)d_in[9];
    const float* Wo_h  = (const float*)d_in[10];
    const float* Wo_x  = (const float*)d_in[11];
    const float* bo    = (const float*)d_in[12];
    float* out = (float*)d_out;

    cudaFuncSetAttribute(lstm_persistent_kernel,
                         cudaFuncAttributeMaxDynamicSharedMemorySize, SMEM_BYTES);

    lstm_persistent_kernel<<<GRID_CTAS, THREADS, SMEM_BYTES>>>(
        x, Wf_h, Wf_x, bf, Wip_h, Wip_x, bip,
        Wit_h, Wit_x, bit_, Wo_h, Wo_x, bo, out);
}